// round 4
// baseline (speedup 1.0000x reference)
#include <cuda_runtime.h>
#include <stdint.h>

#define S_LEN 4096
#define DM    768
#define NH    12
#define HD    64

// Scratch (no cudaMalloc allowed)
__device__ float g_q[S_LEN * DM];
__device__ float g_k[S_LEN * DM];
__device__ float g_v[S_LEN * DM];
__device__ float g_att[S_LEN * DM];

__device__ __forceinline__ uint32_t f2tf(float x) {
    uint32_t r;
    asm("cvt.rna.tf32.f32 %0, %1;" : "=r"(r) : "f"(x));
    return r;
}

__device__ __forceinline__ void mma_tf32(float c[4],
    uint32_t a0, uint32_t a1, uint32_t a2, uint32_t a3,
    uint32_t b0, uint32_t b1)
{
    asm volatile(
        "mma.sync.aligned.m16n8k8.row.col.f32.tf32.tf32.f32 "
        "{%0,%1,%2,%3}, {%4,%5,%6,%7}, {%8,%9}, {%0,%1,%2,%3};"
        : "+f"(c[0]), "+f"(c[1]), "+f"(c[2]), "+f"(c[3])
        : "r"(a0), "r"(a1), "r"(a2), "r"(a3), "r"(b0), "r"(b1));
}

// ---------------------------------------------------------------------------
// GEMM: C[M,N] = A[M,K] @ B[K,N] (+bias). Block 128x64, Ktile 32, 256 thr.
// k-relabel: hw slot tg of chunk-pair c <-> logical cols 16c+4tg..+3 so
// A-fragments are LDS.128. Next tile prefetched into registers during compute.
// ---------------------------------------------------------------------------
#define AST 36
#define BST 70

__global__ __launch_bounds__(256) void gemm_mma(
    const float* __restrict__ A, const float* __restrict__ B,
    const float* __restrict__ bias, float* __restrict__ C,
    int M, int N, int K)
{
    __shared__ uint32_t As[128 * AST];
    __shared__ uint32_t Bs[32 * BST];

    const int tid  = threadIdx.x;
    const int warp = tid >> 5, lane = tid & 31;
    const int g = lane >> 2, tg = lane & 3;
    const int wm = warp >> 1, wn = warp & 1;
    const int m0 = blockIdx.y * 128, n0 = blockIdx.x * 64;
    const int mb = wm * 32, nbw = wn * 32;

    float acc[2][4][4];
#pragma unroll
    for (int mt = 0; mt < 2; mt++)
#pragma unroll
        for (int nt = 0; nt < 4; nt++)
#pragma unroll
            for (int c = 0; c < 4; c++) acc[mt][nt][c] = 0.f;

    float4 ra[4], rb[2];
    // prologue: tile k0 = 0 into registers
#pragma unroll
    for (int it = 0; it < 4; it++) {
        int idx = it * 256 + tid;
        int r = idx >> 3, c4 = (idx & 7) * 4;
        ra[it] = *(const float4*)&A[(size_t)(m0 + r) * K + c4];
    }
#pragma unroll
    for (int it = 0; it < 2; it++) {
        int idx = it * 256 + tid;
        int r = idx >> 4, c4 = (idx & 15) * 4;
        rb[it] = *(const float4*)&B[(size_t)r * N + n0 + c4];
    }

    for (int k0 = 0; k0 < K; k0 += 32) {
        // stage current tile to SMEM
#pragma unroll
        for (int it = 0; it < 4; it++) {
            int idx = it * 256 + tid;
            int r = idx >> 3, c4 = (idx & 7) * 4;
            *(uint4*)&As[r * AST + c4] =
                make_uint4(f2tf(ra[it].x), f2tf(ra[it].y), f2tf(ra[it].z), f2tf(ra[it].w));
        }
#pragma unroll
        for (int it = 0; it < 2; it++) {
            int idx = it * 256 + tid;
            int r = idx >> 4, c4 = (idx & 15) * 4;
            *(uint2*)&Bs[r * BST + c4]     = make_uint2(f2tf(rb[it].x), f2tf(rb[it].y));
            *(uint2*)&Bs[r * BST + c4 + 2] = make_uint2(f2tf(rb[it].z), f2tf(rb[it].w));
        }
        __syncthreads();

        // prefetch next tile (hidden behind the mma loop)
        if (k0 + 32 < K) {
#pragma unroll
            for (int it = 0; it < 4; it++) {
                int idx = it * 256 + tid;
                int r = idx >> 3, c4 = (idx & 7) * 4;
                ra[it] = *(const float4*)&A[(size_t)(m0 + r) * K + k0 + 32 + c4];
            }
#pragma unroll
            for (int it = 0; it < 2; it++) {
                int idx = it * 256 + tid;
                int r = idx >> 4, c4 = (idx & 15) * 4;
                rb[it] = *(const float4*)&B[(size_t)(k0 + 32 + r) * N + n0 + c4];
            }
        }

#pragma unroll
        for (int c = 0; c < 2; c++) {
            uint4 A0[2], A1[2];
#pragma unroll
            for (int mt = 0; mt < 2; mt++) {
                int r = mb + mt * 16 + g;
                A0[mt] = *(uint4*)&As[r * AST + 16 * c + 4 * tg];
                A1[mt] = *(uint4*)&As[(r + 8) * AST + 16 * c + 4 * tg];
            }
#pragma unroll
            for (int nt = 0; nt < 4; nt++) {
                int cn = nbw + nt * 8 + g;
                int rb0 = 16 * c + 4 * tg;
                uint32_t b0 = Bs[(rb0 + 0) * BST + cn];
                uint32_t b1 = Bs[(rb0 + 1) * BST + cn];
                uint32_t b2 = Bs[(rb0 + 2) * BST + cn];
                uint32_t b3 = Bs[(rb0 + 3) * BST + cn];
#pragma unroll
                for (int mt = 0; mt < 2; mt++) {
                    mma_tf32(acc[mt][nt], A0[mt].x, A1[mt].x, A0[mt].y, A1[mt].y, b0, b1);
                    mma_tf32(acc[mt][nt], A0[mt].z, A1[mt].z, A0[mt].w, A1[mt].w, b2, b3);
                }
            }
        }
        __syncthreads();
    }

#pragma unroll
    for (int mt = 0; mt < 2; mt++) {
#pragma unroll
        for (int nt = 0; nt < 4; nt++) {
            int r = m0 + mb + mt * 16 + g;
            int c = n0 + nbw + nt * 8 + 2 * tg;
            float b0 = 0.f, b1 = 0.f;
            if (bias) { b0 = bias[c]; b1 = bias[c + 1]; }
            *(float2*)&C[(size_t)r * N + c] =
                make_float2(acc[mt][nt][0] + b0, acc[mt][nt][1] + b1);
            *(float2*)&C[(size_t)(r + 8) * N + c] =
                make_float2(acc[mt][nt][2] + b0, acc[mt][nt][3] + b1);
        }
    }
}

// ---------------------------------------------------------------------------
// Flash attention, tf32 mma, causal. Block = 128 q-rows x 1 head, 256 thr.
// k-relabel for LDS.128 fragments; V stored transposed (Vt[dv][key]).
// ---------------------------------------------------------------------------
#define QST 68
#define KST 68
#define VTST 68
#define PST 68
#define ATTN_SMEM ((128*QST + 64*KST + 64*VTST + 128*PST) * 4)  // 104448 B

__global__ __launch_bounds__(256, 2) void attn_mma(
    const float* __restrict__ q, const float* __restrict__ k,
    const float* __restrict__ v, float* __restrict__ o)
{
    extern __shared__ uint32_t sm[];
    uint32_t* Qs = sm;                  // [q][d]    128 x QST
    uint32_t* Ks = Qs + 128 * QST;      // [key][d]   64 x KST
    uint32_t* Vt = Ks + 64 * KST;       // [dv][key]  64 x VTST (transposed)
    uint32_t* Ps = Vt + 64 * VTST;      // [q][key]  128 x PST

    const int h = blockIdx.y;
    const int t = blockIdx.x;
    const int iq = (t & 1) ? (31 - (t >> 1)) : (t >> 1);  // heavy/light interleave
    const int tid = threadIdx.x, warp = tid >> 5, lane = tid & 31;
    const int g = lane >> 2, tg = lane & 3;
    const size_t hoff = (size_t)h * HD;
    const int qrow = iq * 128 + warp * 16 + g;   // rows qrow, qrow+8
    const int wrow = warp * 16 + g;

    // Q tile (128 x 64) -> SMEM tf32
#pragma unroll
    for (int it = 0; it < 8; it++) {
        int idx = it * 256 + tid;
        int r = idx >> 4, d4 = (idx & 15) * 4;
        float4 val = *(const float4*)&q[(size_t)(iq * 128 + r) * DM + hoff + d4];
        *(uint4*)&Qs[r * QST + d4] =
            make_uint4(f2tf(val.x), f2tf(val.y), f2tf(val.z), f2tf(val.w));
    }

    float of[8][4];
#pragma unroll
    for (int nt = 0; nt < 8; nt++)
#pragma unroll
        for (int c = 0; c < 4; c++) of[nt][c] = 0.f;
    float m0r = -1e30f, m1r = -1e30f, l0 = 0.f, l1 = 0.f;

    __syncthreads();

    const int ktmax = 2 * iq + 1;
    for (int kt = 0; kt <= ktmax; kt++) {
        // K tile plain [key][d]
#pragma unroll
        for (int it = 0; it < 4; it++) {
            int idx = it * 256 + tid;
            int key = idx >> 4, d4 = (idx & 15) * 4;
            float4 kv = *(const float4*)&k[hoff + (size_t)(kt * 64 + key) * DM + d4];
            *(uint4*)&Ks[key * KST + d4] =
                make_uint4(f2tf(kv.x), f2tf(kv.y), f2tf(kv.z), f2tf(kv.w));
        }
        // V tile transposed [dv][key] (key-major lanes -> conflict-free STS)
#pragma unroll
        for (int it = 0; it < 4; it++) {
            int idx = it * 256 + tid;
            int key = idx & 63, dg = (idx >> 6) * 4;
            float4 vv = *(const float4*)&v[hoff + (size_t)(kt * 64 + key) * DM + dg];
            Vt[(dg + 0) * VTST + key] = f2tf(vv.x);
            Vt[(dg + 1) * VTST + key] = f2tf(vv.y);
            Vt[(dg + 2) * VTST + key] = f2tf(vv.z);
            Vt[(dg + 3) * VTST + key] = f2tf(vv.w);
        }
        __syncthreads();

        // S = Q @ K^T with k-relabel (chunk-pair c covers d-cols 16c..16c+15)
        float s[8][4];
#pragma unroll
        for (int nt = 0; nt < 8; nt++)
#pragma unroll
            for (int c = 0; c < 4; c++) s[nt][c] = 0.f;

#pragma unroll
        for (int c = 0; c < 4; c++) {
            uint4 A0 = *(uint4*)&Qs[wrow * QST + 16 * c + 4 * tg];
            uint4 A1 = *(uint4*)&Qs[(wrow + 8) * QST + 16 * c + 4 * tg];
#pragma unroll
            for (int nt = 0; nt < 8; nt++) {
                uint4 B0 = *(uint4*)&Ks[(nt * 8 + g) * KST + 16 * c + 4 * tg];
                mma_tf32(s[nt], A0.x, A1.x, A0.y, A1.y, B0.x, B0.y);
                mma_tf32(s[nt], A0.z, A1.z, A0.w, A1.w, B0.z, B0.w);
            }
        }

        // scale + causal mask
        const bool need_mask = (kt >= 2 * iq);
#pragma unroll
        for (int nt = 0; nt < 8; nt++) {
            s[nt][0] *= 0.125f; s[nt][1] *= 0.125f;
            s[nt][2] *= 0.125f; s[nt][3] *= 0.125f;
            if (need_mask) {
                int col = kt * 64 + nt * 8 + 2 * tg;
                if (col     > qrow)     s[nt][0] = -1e30f;
                if (col + 1 > qrow)     s[nt][1] = -1e30f;
                if (col     > qrow + 8) s[nt][2] = -1e30f;
                if (col + 1 > qrow + 8) s[nt][3] = -1e30f;
            }
        }

        // online softmax (rows qrow, qrow+8; each spread over 4 tg-lanes)
        float rm0 = -1e30f, rm1 = -1e30f;
#pragma unroll
        for (int nt = 0; nt < 8; nt++) {
            rm0 = fmaxf(rm0, fmaxf(s[nt][0], s[nt][1]));
            rm1 = fmaxf(rm1, fmaxf(s[nt][2], s[nt][3]));
        }
#pragma unroll
        for (int off = 1; off <= 2; off <<= 1) {
            rm0 = fmaxf(rm0, __shfl_xor_sync(0xFFFFFFFFu, rm0, off));
            rm1 = fmaxf(rm1, __shfl_xor_sync(0xFFFFFFFFu, rm1, off));
        }
        float nm0 = fmaxf(m0r, rm0), nm1 = fmaxf(m1r, rm1);
        float al0 = __expf(m0r - nm0), al1 = __expf(m1r - nm1);
        float sum0 = 0.f, sum1 = 0.f;
#pragma unroll
        for (int nt = 0; nt < 8; nt++) {
            s[nt][0] = __expf(s[nt][0] - nm0); sum0 += s[nt][0];
            s[nt][1] = __expf(s[nt][1] - nm0); sum0 += s[nt][1];
            s[nt][2] = __expf(s[nt][2] - nm1); sum1 += s[nt][2];
            s[nt][3] = __expf(s[nt][3] - nm1); sum1 += s[nt][3];
        }
#pragma unroll
        for (int off = 1; off <= 2; off <<= 1) {
            sum0 += __shfl_xor_sync(0xFFFFFFFFu, sum0, off);
            sum1 += __shfl_xor_sync(0xFFFFFFFFu, sum1, off);
        }
        l0 = l0 * al0 + sum0;  l1 = l1 * al1 + sum1;
        m0r = nm0;  m1r = nm1;
#pragma unroll
        for (int nt = 0; nt < 8; nt++) {
            of[nt][0] *= al0; of[nt][1] *= al0;
            of[nt][2] *= al1; of[nt][3] *= al1;
        }

        // stage P (warp-private rows) as tf32, STS.64 pairs
#pragma unroll
        for (int nt = 0; nt < 8; nt++) {
            int pc = nt * 8 + 2 * tg;
            *(uint2*)&Ps[wrow * PST + pc] =
                make_uint2(f2tf(s[nt][0]), f2tf(s[nt][1]));
            *(uint2*)&Ps[(wrow + 8) * PST + pc] =
                make_uint2(f2tf(s[nt][2]), f2tf(s[nt][3]));
        }
        __syncwarp();

        // O += P @ V with k-relabel (chunk-pair c covers keys 16c..16c+15)
#pragma unroll
        for (int c = 0; c < 4; c++) {
            uint4 A0 = *(uint4*)&Ps[wrow * PST + 16 * c + 4 * tg];
            uint4 A1 = *(uint4*)&Ps[(wrow + 8) * PST + 16 * c + 4 * tg];
#pragma unroll
            for (int nt = 0; nt < 8; nt++) {
                uint4 B0 = *(uint4*)&Vt[(nt * 8 + g) * VTST + 16 * c + 4 * tg];
                mma_tf32(of[nt], A0.x, A1.x, A0.y, A1.y, B0.x, B0.y);
                mma_tf32(of[nt], A0.z, A1.z, A0.w, A1.w, B0.z, B0.w);
            }
        }
        __syncthreads();   // protect Ks/Vt before next tile load
    }

    // epilogue
    float inv0 = 1.f / l0, inv1 = 1.f / l1;
#pragma unroll
    for (int nt = 0; nt < 8; nt++) {
        size_t c = hoff + nt * 8 + 2 * tg;
        *(float2*)&o[(size_t)qrow * DM + c] =
            make_float2(of[nt][0] * inv0, of[nt][1] * inv0);
        *(float2*)&o[(size_t)(qrow + 8) * DM + c] =
            make_float2(of[nt][2] * inv1, of[nt][3] * inv1);
    }
}

// ---------------------------------------------------------------------------
// Launch
// ---------------------------------------------------------------------------
extern "C" void kernel_launch(void* const* d_in, const int* in_sizes, int n_in,
                              void* d_out, int out_size)
{
    const float* Q  = (const float*)d_in[0];
    const float* K  = (const float*)d_in[1];
    const float* V  = (const float*)d_in[2];
    const float* Wq = (const float*)d_in[3];
    const float* Wk = (const float*)d_in[4];
    const float* Wv = (const float*)d_in[5];
    const float* Wo = (const float*)d_in[6];
    const float* bo = (const float*)d_in[7];
    float* out = (float*)d_out;

    float *gq, *gk, *gv, *ga;
    cudaGetSymbolAddress((void**)&gq, g_q);
    cudaGetSymbolAddress((void**)&gk, g_k);
    cudaGetSymbolAddress((void**)&gv, g_v);
    cudaGetSymbolAddress((void**)&ga, g_att);

    static bool attr_set = false;
    if (!attr_set) {
        cudaFuncSetAttribute(attn_mma,
                             cudaFuncAttributeMaxDynamicSharedMemorySize,
                             ATTN_SMEM);
        attr_set = true;
    }

    dim3 gproj(DM / 64, S_LEN / 128);   // (12, 32)
    gemm_mma<<<gproj, 256>>>(Q, Wq, nullptr, gq, S_LEN, DM, DM);
    gemm_mma<<<gproj, 256>>>(K, Wk, nullptr, gk, S_LEN, DM, DM);
    gemm_mma<<<gproj, 256>>>(V, Wv, nullptr, gv, S_LEN, DM, DM);

    dim3 gattn(S_LEN / 128, NH);        // (32, 12)
    attn_mma<<<gattn, 256, ATTN_SMEM>>>(gq, gk, gv, ga);

    gemm_mma<<<gproj, 256>>>(ga, Wo, bo, out, S_LEN, DM, DM);
}

// round 5
// speedup vs baseline: 1.4332x; 1.4332x over previous
#include <cuda_runtime.h>
#include <stdint.h>

#define S_LEN 4096
#define DM    768
#define NH    12
#define HD    64

// Scratch (no cudaMalloc allowed)
__device__ float g_q[S_LEN * DM];
__device__ float g_k[S_LEN * DM];
__device__ float g_v[S_LEN * DM];
__device__ float g_att[S_LEN * DM];

__device__ __forceinline__ uint32_t f2tf(float x) {
    uint32_t r;
    asm("cvt.rna.tf32.f32 %0, %1;" : "=r"(r) : "f"(x));
    return r;
}

__device__ __forceinline__ void mma_tf32(float c[4],
    uint32_t a0, uint32_t a1, uint32_t a2, uint32_t a3,
    uint32_t b0, uint32_t b1)
{
    asm volatile(
        "mma.sync.aligned.m16n8k8.row.col.f32.tf32.tf32.f32 "
        "{%0,%1,%2,%3}, {%4,%5,%6,%7}, {%8,%9}, {%0,%1,%2,%3};"
        : "+f"(c[0]), "+f"(c[1]), "+f"(c[2]), "+f"(c[3])
        : "r"(a0), "r"(a1), "r"(a2), "r"(a3), "r"(b0), "r"(b1));
}

// ---------------------------------------------------------------------------
// GEMM: C[M,N] = A[M,K] @ B[K,N] (+bias). Block 128x64, Ktile 32, 256 thr.
// Round-3 fragment layout (conflict-free scalar LDS) + register prefetch.
// ---------------------------------------------------------------------------
#define AST 36
#define BST 72

__global__ __launch_bounds__(256) void gemm_mma(
    const float* __restrict__ A, const float* __restrict__ B,
    const float* __restrict__ bias, float* __restrict__ C,
    int M, int N, int K)
{
    __shared__ uint32_t As[128 * AST];
    __shared__ uint32_t Bs[32 * BST];

    const int tid  = threadIdx.x;
    const int warp = tid >> 5, lane = tid & 31;
    const int g = lane >> 2, tg = lane & 3;
    const int wm = warp >> 1, wn = warp & 1;
    const int m0 = blockIdx.y * 128, n0 = blockIdx.x * 64;
    const int mb = wm * 32, nbw = wn * 32;

    float acc[2][4][4];
#pragma unroll
    for (int mt = 0; mt < 2; mt++)
#pragma unroll
        for (int nt = 0; nt < 4; nt++)
#pragma unroll
            for (int c = 0; c < 4; c++) acc[mt][nt][c] = 0.f;

    float4 ra[4], rb[2];
#pragma unroll
    for (int it = 0; it < 4; it++) {
        int idx = it * 256 + tid;
        int r = idx >> 3, c4 = (idx & 7) * 4;
        ra[it] = *(const float4*)&A[(size_t)(m0 + r) * K + c4];
    }
#pragma unroll
    for (int it = 0; it < 2; it++) {
        int idx = it * 256 + tid;
        int r = idx >> 4, c4 = (idx & 15) * 4;
        rb[it] = *(const float4*)&B[(size_t)r * N + n0 + c4];
    }

    for (int k0 = 0; k0 < K; k0 += 32) {
        // stage current tile
#pragma unroll
        for (int it = 0; it < 4; it++) {
            int idx = it * 256 + tid;
            int r = idx >> 3, c4 = (idx & 7) * 4;
            *(uint4*)&As[r * AST + c4] =
                make_uint4(f2tf(ra[it].x), f2tf(ra[it].y), f2tf(ra[it].z), f2tf(ra[it].w));
        }
#pragma unroll
        for (int it = 0; it < 2; it++) {
            int idx = it * 256 + tid;
            int r = idx >> 4, c4 = (idx & 15) * 4;
            *(uint4*)&Bs[r * BST + c4] =
                make_uint4(f2tf(rb[it].x), f2tf(rb[it].y), f2tf(rb[it].z), f2tf(rb[it].w));
        }
        __syncthreads();

        // prefetch next tile
        if (k0 + 32 < K) {
#pragma unroll
            for (int it = 0; it < 4; it++) {
                int idx = it * 256 + tid;
                int r = idx >> 3, c4 = (idx & 7) * 4;
                ra[it] = *(const float4*)&A[(size_t)(m0 + r) * K + k0 + 32 + c4];
            }
#pragma unroll
            for (int it = 0; it < 2; it++) {
                int idx = it * 256 + tid;
                int r = idx >> 4, c4 = (idx & 15) * 4;
                rb[it] = *(const float4*)&B[(size_t)(k0 + 32 + r) * N + n0 + c4];
            }
        }

#pragma unroll
        for (int kk = 0; kk < 4; kk++) {
            uint32_t a[2][4], b[4][2];
#pragma unroll
            for (int mt = 0; mt < 2; mt++) {
                int r = mb + mt * 16 + g;
                int kc = kk * 8 + tg;
                a[mt][0] = As[r * AST + kc];
                a[mt][1] = As[(r + 8) * AST + kc];
                a[mt][2] = As[r * AST + kc + 4];
                a[mt][3] = As[(r + 8) * AST + kc + 4];
            }
#pragma unroll
            for (int nt = 0; nt < 4; nt++) {
                int c = nbw + nt * 8 + g;
                b[nt][0] = Bs[(kk * 8 + tg) * BST + c];
                b[nt][1] = Bs[(kk * 8 + tg + 4) * BST + c];
            }
#pragma unroll
            for (int mt = 0; mt < 2; mt++)
#pragma unroll
                for (int nt = 0; nt < 4; nt++)
                    mma_tf32(acc[mt][nt], a[mt][0], a[mt][1], a[mt][2], a[mt][3],
                             b[nt][0], b[nt][1]);
        }
        __syncthreads();
    }

#pragma unroll
    for (int mt = 0; mt < 2; mt++) {
#pragma unroll
        for (int nt = 0; nt < 4; nt++) {
            int r = m0 + mb + mt * 16 + g;
            int c = n0 + nbw + nt * 8 + 2 * tg;
            float b0 = 0.f, b1 = 0.f;
            if (bias) { b0 = bias[c]; b1 = bias[c + 1]; }
            *(float2*)&C[(size_t)r * N + c] =
                make_float2(acc[mt][nt][0] + b0, acc[mt][nt][1] + b1);
            *(float2*)&C[(size_t)(r + 8) * N + c] =
                make_float2(acc[mt][nt][2] + b0, acc[mt][nt][3] + b1);
        }
    }
}

// ---------------------------------------------------------------------------
// Flash attention, tf32 mma, causal. Block = 128 q-rows x 1 head, 256 thr.
// Round-3 layout (scalar conflict-free LDS) + K/V register prefetch: LDGs for
// tile kt+1 issued after the P-store (s[] dead), consumed next iteration.
// ---------------------------------------------------------------------------
#define QST 68
#define KST 68
#define VST 72
#define PST 68
#define ATTN_SMEM ((128*QST + 64*KST + 64*VST + 128*PST) * 4)  // 105472 B

__global__ __launch_bounds__(256, 2) void attn_mma(
    const float* __restrict__ q, const float* __restrict__ k,
    const float* __restrict__ v, float* __restrict__ o)
{
    extern __shared__ uint32_t sm[];
    uint32_t* Qs = sm;                  // [q][d]   128 x QST
    uint32_t* Ks = Qs + 128 * QST;      // [key][d]  64 x KST
    uint32_t* Vs = Ks + 64 * KST;       // [key][dv] 64 x VST
    uint32_t* Ps = Vs + 64 * VST;       // [q][key] 128 x PST

    const int h = blockIdx.y;
    const int t = blockIdx.x;
    const int iq = (t & 1) ? (31 - (t >> 1)) : (t >> 1);  // heavy/light interleave
    const int tid = threadIdx.x, warp = tid >> 5, lane = tid & 31;
    const int g = lane >> 2, tg = lane & 3;
    const size_t hoff = (size_t)h * HD;
    const int qrow = iq * 128 + warp * 16 + g;   // rows qrow, qrow+8
    const int wrow = warp * 16 + g;

    // per-thread K/V staging coordinates (same mapping as the SMEM store)
    const int skey = tid >> 4;              // idx>>4 for it-th chunk: skey + it*16
    const int sd4  = (tid & 15) * 4;

    // Q tile (128 x 64) -> SMEM tf32
#pragma unroll
    for (int it = 0; it < 8; it++) {
        int idx = it * 256 + tid;
        int r = idx >> 4, d4 = (idx & 15) * 4;
        float4 val = *(const float4*)&q[(size_t)(iq * 128 + r) * DM + hoff + d4];
        *(uint4*)&Qs[r * QST + d4] =
            make_uint4(f2tf(val.x), f2tf(val.y), f2tf(val.z), f2tf(val.w));
    }

    float of[8][4];
#pragma unroll
    for (int nt = 0; nt < 8; nt++)
#pragma unroll
        for (int c = 0; c < 4; c++) of[nt][c] = 0.f;
    float m0r = -1e30f, m1r = -1e30f, l0 = 0.f, l1 = 0.f;

    // prologue: prefetch tile 0 into registers
    float4 pk[4], pv[4];
#pragma unroll
    for (int it = 0; it < 4; it++) {
        size_t gidx = hoff + (size_t)(it * 16 + skey) * DM + sd4;
        pk[it] = *(const float4*)&k[gidx];
        pv[it] = *(const float4*)&v[gidx];
    }

    __syncthreads();

    const int ktmax = 2 * iq + 1;
    for (int kt = 0; kt <= ktmax; kt++) {
        // stage prefetched K/V tile to SMEM
#pragma unroll
        for (int it = 0; it < 4; it++) {
            int key = it * 16 + skey;
            *(uint4*)&Ks[key * KST + sd4] =
                make_uint4(f2tf(pk[it].x), f2tf(pk[it].y), f2tf(pk[it].z), f2tf(pk[it].w));
            *(uint4*)&Vs[key * VST + sd4] =
                make_uint4(f2tf(pv[it].x), f2tf(pv[it].y), f2tf(pv[it].z), f2tf(pv[it].w));
        }
        __syncthreads();

        // S = Q @ K^T   (warp: 16 rows x 64 keys = 8 n-tiles)
        float s[8][4];
#pragma unroll
        for (int nt = 0; nt < 8; nt++)
#pragma unroll
            for (int c = 0; c < 4; c++) s[nt][c] = 0.f;

#pragma unroll
        for (int ks = 0; ks < 8; ks++) {
            int kc = ks * 8 + tg;
            uint32_t a0 = Qs[wrow * QST + kc];
            uint32_t a1 = Qs[(wrow + 8) * QST + kc];
            uint32_t a2 = Qs[wrow * QST + kc + 4];
            uint32_t a3 = Qs[(wrow + 8) * QST + kc + 4];
#pragma unroll
            for (int nt = 0; nt < 8; nt++) {
                uint32_t b0 = Ks[(nt * 8 + g) * KST + kc];
                uint32_t b1 = Ks[(nt * 8 + g) * KST + kc + 4];
                mma_tf32(s[nt], a0, a1, a2, a3, b0, b1);
            }
        }

        // scale + causal mask
        const bool need_mask = (kt >= 2 * iq);
#pragma unroll
        for (int nt = 0; nt < 8; nt++) {
            s[nt][0] *= 0.125f; s[nt][1] *= 0.125f;
            s[nt][2] *= 0.125f; s[nt][3] *= 0.125f;
            if (need_mask) {
                int col = kt * 64 + nt * 8 + 2 * tg;
                if (col     > qrow)     s[nt][0] = -1e30f;
                if (col + 1 > qrow)     s[nt][1] = -1e30f;
                if (col     > qrow + 8) s[nt][2] = -1e30f;
                if (col + 1 > qrow + 8) s[nt][3] = -1e30f;
            }
        }

        // online softmax (rows qrow, qrow+8; each spread over 4 tg-lanes)
        float rm0 = -1e30f, rm1 = -1e30f;
#pragma unroll
        for (int nt = 0; nt < 8; nt++) {
            rm0 = fmaxf(rm0, fmaxf(s[nt][0], s[nt][1]));
            rm1 = fmaxf(rm1, fmaxf(s[nt][2], s[nt][3]));
        }
#pragma unroll
        for (int off = 1; off <= 2; off <<= 1) {
            rm0 = fmaxf(rm0, __shfl_xor_sync(0xFFFFFFFFu, rm0, off));
            rm1 = fmaxf(rm1, __shfl_xor_sync(0xFFFFFFFFu, rm1, off));
        }
        float nm0 = fmaxf(m0r, rm0), nm1 = fmaxf(m1r, rm1);
        float al0 = __expf(m0r - nm0), al1 = __expf(m1r - nm1);
        float sum0 = 0.f, sum1 = 0.f;
#pragma unroll
        for (int nt = 0; nt < 8; nt++) {
            s[nt][0] = __expf(s[nt][0] - nm0); sum0 += s[nt][0];
            s[nt][1] = __expf(s[nt][1] - nm0); sum0 += s[nt][1];
            s[nt][2] = __expf(s[nt][2] - nm1); sum1 += s[nt][2];
            s[nt][3] = __expf(s[nt][3] - nm1); sum1 += s[nt][3];
        }
#pragma unroll
        for (int off = 1; off <= 2; off <<= 1) {
            sum0 += __shfl_xor_sync(0xFFFFFFFFu, sum0, off);
            sum1 += __shfl_xor_sync(0xFFFFFFFFu, sum1, off);
        }
        l0 = l0 * al0 + sum0;  l1 = l1 * al1 + sum1;
        m0r = nm0;  m1r = nm1;
#pragma unroll
        for (int nt = 0; nt < 8; nt++) {
            of[nt][0] *= al0; of[nt][1] *= al0;
            of[nt][2] *= al1; of[nt][3] *= al1;
        }

        // stage P (warp-private rows) as tf32
#pragma unroll
        for (int nt = 0; nt < 8; nt++) {
            int pc = nt * 8 + 2 * tg;
            *(uint2*)&Ps[wrow * PST + pc] =
                make_uint2(f2tf(s[nt][0]), f2tf(s[nt][1]));
            *(uint2*)&Ps[(wrow + 8) * PST + pc] =
                make_uint2(f2tf(s[nt][2]), f2tf(s[nt][3]));
        }
        __syncwarp();

        // prefetch next K/V tile (s[] registers are dead now; latency hides
        // behind the PV-mma below and the next S-mma)
        if (kt < ktmax) {
#pragma unroll
            for (int it = 0; it < 4; it++) {
                size_t gidx = hoff + (size_t)((kt + 1) * 64 + it * 16 + skey) * DM + sd4;
                pk[it] = *(const float4*)&k[gidx];
                pv[it] = *(const float4*)&v[gidx];
            }
        }

        // O += P @ V
#pragma unroll
        for (int ks = 0; ks < 8; ks++) {
            int kc = ks * 8 + tg;
            uint32_t a0 = Ps[wrow * PST + kc];
            uint32_t a1 = Ps[(wrow + 8) * PST + kc];
            uint32_t a2 = Ps[wrow * PST + kc + 4];
            uint32_t a3 = Ps[(wrow + 8) * PST + kc + 4];
#pragma unroll
            for (int nt = 0; nt < 8; nt++) {
                uint32_t b0 = Vs[kc * VST + nt * 8 + g];
                uint32_t b1 = Vs[(kc + 4) * VST + nt * 8 + g];
                mma_tf32(of[nt], a0, a1, a2, a3, b0, b1);
            }
        }
        __syncthreads();   // protect Ks/Vs before next tile store
    }

    // epilogue
    float inv0 = 1.f / l0, inv1 = 1.f / l1;
#pragma unroll
    for (int nt = 0; nt < 8; nt++) {
        size_t c = hoff + nt * 8 + 2 * tg;
        *(float2*)&o[(size_t)qrow * DM + c] =
            make_float2(of[nt][0] * inv0, of[nt][1] * inv0);
        *(float2*)&o[(size_t)(qrow + 8) * DM + c] =
            make_float2(of[nt][2] * inv1, of[nt][3] * inv1);
    }
}

// ---------------------------------------------------------------------------
// Launch
// ---------------------------------------------------------------------------
extern "C" void kernel_launch(void* const* d_in, const int* in_sizes, int n_in,
                              void* d_out, int out_size)
{
    const float* Q  = (const float*)d_in[0];
    const float* K  = (const float*)d_in[1];
    const float* V  = (const float*)d_in[2];
    const float* Wq = (const float*)d_in[3];
    const float* Wk = (const float*)d_in[4];
    const float* Wv = (const float*)d_in[5];
    const float* Wo = (const float*)d_in[6];
    const float* bo = (const float*)d_in[7];
    float* out = (float*)d_out;

    float *gq, *gk, *gv, *ga;
    cudaGetSymbolAddress((void**)&gq, g_q);
    cudaGetSymbolAddress((void**)&gk, g_k);
    cudaGetSymbolAddress((void**)&gv, g_v);
    cudaGetSymbolAddress((void**)&ga, g_att);

    static bool attr_set = false;
    if (!attr_set) {
        cudaFuncSetAttribute(attn_mma,
                             cudaFuncAttributeMaxDynamicSharedMemorySize,
                             ATTN_SMEM);
        attr_set = true;
    }

    dim3 gproj(DM / 64, S_LEN / 128);   // (12, 32)
    gemm_mma<<<gproj, 256>>>(Q, Wq, nullptr, gq, S_LEN, DM, DM);
    gemm_mma<<<gproj, 256>>>(K, Wk, nullptr, gk, S_LEN, DM, DM);
    gemm_mma<<<gproj, 256>>>(V, Wv, nullptr, gv, S_LEN, DM, DM);

    dim3 gattn(S_LEN / 128, NH);        // (32, 12)
    attn_mma<<<gattn, 256, ATTN_SMEM>>>(gq, gk, gv, ga);

    gemm_mma<<<gproj, 256>>>(ga, Wo, bo, out, S_LEN, DM, DM);
}

// round 6
// speedup vs baseline: 1.5426x; 1.0763x over previous
#include <cuda_runtime.h>
#include <stdint.h>

#define S_LEN 4096
#define DM    768
#define NH    12
#define HD    64

// Scratch (no cudaMalloc allowed)
__device__ float g_q[S_LEN * DM];
__device__ float g_k[S_LEN * DM];
__device__ float g_v[S_LEN * DM];
__device__ float g_att[S_LEN * DM];

__device__ __forceinline__ uint32_t f2tf(float x) {
    uint32_t r;
    asm("cvt.rna.tf32.f32 %0, %1;" : "=r"(r) : "f"(x));
    return r;
}

__device__ __forceinline__ void mma_tf32(float c[4],
    uint32_t a0, uint32_t a1, uint32_t a2, uint32_t a3,
    uint32_t b0, uint32_t b1)
{
    asm volatile(
        "mma.sync.aligned.m16n8k8.row.col.f32.tf32.tf32.f32 "
        "{%0,%1,%2,%3}, {%4,%5,%6,%7}, {%8,%9}, {%0,%1,%2,%3};"
        : "+f"(c[0]), "+f"(c[1]), "+f"(c[2]), "+f"(c[3])
        : "r"(a0), "r"(a1), "r"(a2), "r"(a3), "r"(b0), "r"(b1));
}

// ---------------------------------------------------------------------------
// GEMM: unchanged from round 5 (known good).
// ---------------------------------------------------------------------------
#define AST 36
#define BST 72

__global__ __launch_bounds__(256) void gemm_mma(
    const float* __restrict__ A, const float* __restrict__ B,
    const float* __restrict__ bias, float* __restrict__ C,
    int M, int N, int K)
{
    __shared__ uint32_t As[128 * AST];
    __shared__ uint32_t Bs[32 * BST];

    const int tid  = threadIdx.x;
    const int warp = tid >> 5, lane = tid & 31;
    const int g = lane >> 2, tg = lane & 3;
    const int wm = warp >> 1, wn = warp & 1;
    const int m0 = blockIdx.y * 128, n0 = blockIdx.x * 64;
    const int mb = wm * 32, nbw = wn * 32;

    float acc[2][4][4];
#pragma unroll
    for (int mt = 0; mt < 2; mt++)
#pragma unroll
        for (int nt = 0; nt < 4; nt++)
#pragma unroll
            for (int c = 0; c < 4; c++) acc[mt][nt][c] = 0.f;

    float4 ra[4], rb[2];
#pragma unroll
    for (int it = 0; it < 4; it++) {
        int idx = it * 256 + tid;
        int r = idx >> 3, c4 = (idx & 7) * 4;
        ra[it] = *(const float4*)&A[(size_t)(m0 + r) * K + c4];
    }
#pragma unroll
    for (int it = 0; it < 2; it++) {
        int idx = it * 256 + tid;
        int r = idx >> 4, c4 = (idx & 15) * 4;
        rb[it] = *(const float4*)&B[(size_t)r * N + n0 + c4];
    }

    for (int k0 = 0; k0 < K; k0 += 32) {
#pragma unroll
        for (int it = 0; it < 4; it++) {
            int idx = it * 256 + tid;
            int r = idx >> 3, c4 = (idx & 7) * 4;
            *(uint4*)&As[r * AST + c4] =
                make_uint4(f2tf(ra[it].x), f2tf(ra[it].y), f2tf(ra[it].z), f2tf(ra[it].w));
        }
#pragma unroll
        for (int it = 0; it < 2; it++) {
            int idx = it * 256 + tid;
            int r = idx >> 4, c4 = (idx & 15) * 4;
            *(uint4*)&Bs[r * BST + c4] =
                make_uint4(f2tf(rb[it].x), f2tf(rb[it].y), f2tf(rb[it].z), f2tf(rb[it].w));
        }
        __syncthreads();

        if (k0 + 32 < K) {
#pragma unroll
            for (int it = 0; it < 4; it++) {
                int idx = it * 256 + tid;
                int r = idx >> 3, c4 = (idx & 7) * 4;
                ra[it] = *(const float4*)&A[(size_t)(m0 + r) * K + k0 + 32 + c4];
            }
#pragma unroll
            for (int it = 0; it < 2; it++) {
                int idx = it * 256 + tid;
                int r = idx >> 4, c4 = (idx & 15) * 4;
                rb[it] = *(const float4*)&B[(size_t)(k0 + 32 + r) * N + n0 + c4];
            }
        }

#pragma unroll
        for (int kk = 0; kk < 4; kk++) {
            uint32_t a[2][4], b[4][2];
#pragma unroll
            for (int mt = 0; mt < 2; mt++) {
                int r = mb + mt * 16 + g;
                int kc = kk * 8 + tg;
                a[mt][0] = As[r * AST + kc];
                a[mt][1] = As[(r + 8) * AST + kc];
                a[mt][2] = As[r * AST + kc + 4];
                a[mt][3] = As[(r + 8) * AST + kc + 4];
            }
#pragma unroll
            for (int nt = 0; nt < 4; nt++) {
                int c = nbw + nt * 8 + g;
                b[nt][0] = Bs[(kk * 8 + tg) * BST + c];
                b[nt][1] = Bs[(kk * 8 + tg + 4) * BST + c];
            }
#pragma unroll
            for (int mt = 0; mt < 2; mt++)
#pragma unroll
                for (int nt = 0; nt < 4; nt++)
                    mma_tf32(acc[mt][nt], a[mt][0], a[mt][1], a[mt][2], a[mt][3],
                             b[nt][0], b[nt][1]);
        }
        __syncthreads();
    }

#pragma unroll
    for (int mt = 0; mt < 2; mt++) {
#pragma unroll
        for (int nt = 0; nt < 4; nt++) {
            int r = m0 + mb + mt * 16 + g;
            int c = n0 + nbw + nt * 8 + 2 * tg;
            float b0 = 0.f, b1 = 0.f;
            if (bias) { b0 = bias[c]; b1 = bias[c + 1]; }
            *(float2*)&C[(size_t)r * N + c] =
                make_float2(acc[mt][nt][0] + b0, acc[mt][nt][1] + b1);
            *(float2*)&C[(size_t)(r + 8) * N + c] =
                make_float2(acc[mt][nt][2] + b0, acc[mt][nt][3] + b1);
        }
    }
}

// ---------------------------------------------------------------------------
// Flash attention, tf32 mma, causal. Block = 128 q-rows x 1 head, 128 thr
// (4 warps x 32 rows each): K/V B-fragments amortized over 2 m-tiles ->
// 1.5 LDS per mma (was 2.5). Round-3 conflict-free layouts; K/V prefetch.
// ---------------------------------------------------------------------------
#define QST 68
#define KST 68
#define VST 72
#define PST 68
#define ATTN_SMEM ((128*QST + 64*KST + 64*VST + 128*PST) * 4)  // 105472 B

__global__ __launch_bounds__(128, 2) void attn_mma(
    const float* __restrict__ q, const float* __restrict__ k,
    const float* __restrict__ v, float* __restrict__ o)
{
    extern __shared__ uint32_t sm[];
    uint32_t* Qs = sm;                  // [q][d]   128 x QST
    uint32_t* Ks = Qs + 128 * QST;      // [key][d]  64 x KST
    uint32_t* Vs = Ks + 64 * KST;       // [key][dv] 64 x VST
    uint32_t* Ps = Vs + 64 * VST;       // [q][key] 128 x PST

    const int h = blockIdx.y;
    const int t = blockIdx.x;
    const int iq = (t & 1) ? (31 - (t >> 1)) : (t >> 1);  // heavy/light interleave
    const int tid = threadIdx.x, warp = tid >> 5, lane = tid & 31;
    const int g = lane >> 2, tg = lane & 3;
    const size_t hoff = (size_t)h * HD;
    const int wbase = warp * 32;                 // warp owns rows wbase..wbase+31
    const int qrow0 = iq * 128 + wbase + g;      // thread rows: +0,+8,+16,+24

    // per-thread K/V staging coords (8 chunks of 8 keys each)
    const int skey = tid >> 4;              // 0..7
    const int sd4  = (tid & 15) * 4;        // 0..60

    // Q tile (128 x 64 = 2048 float4, 128 thr -> 16 iters)
#pragma unroll
    for (int it = 0; it < 16; it++) {
        int idx = it * 128 + tid;
        int r = idx >> 4, d4 = (idx & 15) * 4;
        float4 val = *(const float4*)&q[(size_t)(iq * 128 + r) * DM + hoff + d4];
        *(uint4*)&Qs[r * QST + d4] =
            make_uint4(f2tf(val.x), f2tf(val.y), f2tf(val.z), f2tf(val.w));
    }

    float of[2][8][4];
#pragma unroll
    for (int mt = 0; mt < 2; mt++)
#pragma unroll
        for (int nt = 0; nt < 8; nt++)
#pragma unroll
            for (int c = 0; c < 4; c++) of[mt][nt][c] = 0.f;
    float mrow[2][2], lrow[2][2];
#pragma unroll
    for (int mt = 0; mt < 2; mt++) {
        mrow[mt][0] = mrow[mt][1] = -1e30f;
        lrow[mt][0] = lrow[mt][1] = 0.f;
    }

    // prologue: prefetch tile 0
    float4 pk[8], pv[8];
#pragma unroll
    for (int it = 0; it < 8; it++) {
        size_t gidx = hoff + (size_t)(it * 8 + skey) * DM + sd4;
        pk[it] = *(const float4*)&k[gidx];
        pv[it] = *(const float4*)&v[gidx];
    }

    __syncthreads();

    const int ktmax = 2 * iq + 1;
    for (int kt = 0; kt <= ktmax; kt++) {
        // stage prefetched K/V tile
#pragma unroll
        for (int it = 0; it < 8; it++) {
            int key = it * 8 + skey;
            *(uint4*)&Ks[key * KST + sd4] =
                make_uint4(f2tf(pk[it].x), f2tf(pk[it].y), f2tf(pk[it].z), f2tf(pk[it].w));
            *(uint4*)&Vs[key * VST + sd4] =
                make_uint4(f2tf(pv[it].x), f2tf(pv[it].y), f2tf(pv[it].z), f2tf(pv[it].w));
        }
        __syncthreads();

        // S = Q @ K^T  (warp: 32 rows x 64 keys = 2 m-tiles x 8 n-tiles)
        float s[2][8][4];
#pragma unroll
        for (int mt = 0; mt < 2; mt++)
#pragma unroll
            for (int nt = 0; nt < 8; nt++)
#pragma unroll
                for (int c = 0; c < 4; c++) s[mt][nt][c] = 0.f;

#pragma unroll
        for (int ks = 0; ks < 8; ks++) {
            int kc = ks * 8 + tg;
            uint32_t a[2][4];
#pragma unroll
            for (int mt = 0; mt < 2; mt++) {
                int wr = wbase + mt * 16 + g;
                a[mt][0] = Qs[wr * QST + kc];
                a[mt][1] = Qs[(wr + 8) * QST + kc];
                a[mt][2] = Qs[wr * QST + kc + 4];
                a[mt][3] = Qs[(wr + 8) * QST + kc + 4];
            }
#pragma unroll
            for (int nt = 0; nt < 8; nt++) {
                uint32_t b0 = Ks[(nt * 8 + g) * KST + kc];
                uint32_t b1 = Ks[(nt * 8 + g) * KST + kc + 4];
                mma_tf32(s[0][nt], a[0][0], a[0][1], a[0][2], a[0][3], b0, b1);
                mma_tf32(s[1][nt], a[1][0], a[1][1], a[1][2], a[1][3], b0, b1);
            }
        }

        // scale + causal mask
        const bool need_mask = (kt >= 2 * iq);
#pragma unroll
        for (int mt = 0; mt < 2; mt++) {
            int r0 = qrow0 + mt * 16;
#pragma unroll
            for (int nt = 0; nt < 8; nt++) {
                s[mt][nt][0] *= 0.125f; s[mt][nt][1] *= 0.125f;
                s[mt][nt][2] *= 0.125f; s[mt][nt][3] *= 0.125f;
                if (need_mask) {
                    int col = kt * 64 + nt * 8 + 2 * tg;
                    if (col     > r0)     s[mt][nt][0] = -1e30f;
                    if (col + 1 > r0)     s[mt][nt][1] = -1e30f;
                    if (col     > r0 + 8) s[mt][nt][2] = -1e30f;
                    if (col + 1 > r0 + 8) s[mt][nt][3] = -1e30f;
                }
            }
        }

        // online softmax (4 rows per thread, each spread over 4 tg-lanes)
#pragma unroll
        for (int mt = 0; mt < 2; mt++) {
            float rm0 = -1e30f, rm1 = -1e30f;
#pragma unroll
            for (int nt = 0; nt < 8; nt++) {
                rm0 = fmaxf(rm0, fmaxf(s[mt][nt][0], s[mt][nt][1]));
                rm1 = fmaxf(rm1, fmaxf(s[mt][nt][2], s[mt][nt][3]));
            }
#pragma unroll
            for (int off = 1; off <= 2; off <<= 1) {
                rm0 = fmaxf(rm0, __shfl_xor_sync(0xFFFFFFFFu, rm0, off));
                rm1 = fmaxf(rm1, __shfl_xor_sync(0xFFFFFFFFu, rm1, off));
            }
            float nm0 = fmaxf(mrow[mt][0], rm0), nm1 = fmaxf(mrow[mt][1], rm1);
            float al0 = __expf(mrow[mt][0] - nm0), al1 = __expf(mrow[mt][1] - nm1);
            float sum0 = 0.f, sum1 = 0.f;
#pragma unroll
            for (int nt = 0; nt < 8; nt++) {
                s[mt][nt][0] = __expf(s[mt][nt][0] - nm0); sum0 += s[mt][nt][0];
                s[mt][nt][1] = __expf(s[mt][nt][1] - nm0); sum0 += s[mt][nt][1];
                s[mt][nt][2] = __expf(s[mt][nt][2] - nm1); sum1 += s[mt][nt][2];
                s[mt][nt][3] = __expf(s[mt][nt][3] - nm1); sum1 += s[mt][nt][3];
            }
#pragma unroll
            for (int off = 1; off <= 2; off <<= 1) {
                sum0 += __shfl_xor_sync(0xFFFFFFFFu, sum0, off);
                sum1 += __shfl_xor_sync(0xFFFFFFFFu, sum1, off);
            }
            lrow[mt][0] = lrow[mt][0] * al0 + sum0;
            lrow[mt][1] = lrow[mt][1] * al1 + sum1;
            mrow[mt][0] = nm0;  mrow[mt][1] = nm1;
#pragma unroll
            for (int nt = 0; nt < 8; nt++) {
                of[mt][nt][0] *= al0; of[mt][nt][1] *= al0;
                of[mt][nt][2] *= al1; of[mt][nt][3] *= al1;
            }
        }

        // stage P (warp-private rows) as tf32
#pragma unroll
        for (int mt = 0; mt < 2; mt++) {
            int wr = wbase + mt * 16 + g;
#pragma unroll
            for (int nt = 0; nt < 8; nt++) {
                int pc = nt * 8 + 2 * tg;
                *(uint2*)&Ps[wr * PST + pc] =
                    make_uint2(f2tf(s[mt][nt][0]), f2tf(s[mt][nt][1]));
                *(uint2*)&Ps[(wr + 8) * PST + pc] =
                    make_uint2(f2tf(s[mt][nt][2]), f2tf(s[mt][nt][3]));
            }
        }
        __syncwarp();

        // prefetch next K/V tile (s[] dead; latency hides behind PV + next S)
        if (kt < ktmax) {
#pragma unroll
            for (int it = 0; it < 8; it++) {
                size_t gidx = hoff + (size_t)((kt + 1) * 64 + it * 8 + skey) * DM + sd4;
                pk[it] = *(const float4*)&k[gidx];
                pv[it] = *(const float4*)&v[gidx];
            }
        }

        // O += P @ V
#pragma unroll
        for (int ks = 0; ks < 8; ks++) {
            int kc = ks * 8 + tg;
            uint32_t a[2][4];
#pragma unroll
            for (int mt = 0; mt < 2; mt++) {
                int wr = wbase + mt * 16 + g;
                a[mt][0] = Ps[wr * PST + kc];
                a[mt][1] = Ps[(wr + 8) * PST + kc];
                a[mt][2] = Ps[wr * PST + kc + 4];
                a[mt][3] = Ps[(wr + 8) * PST + kc + 4];
            }
#pragma unroll
            for (int nt = 0; nt < 8; nt++) {
                uint32_t b0 = Vs[kc * VST + nt * 8 + g];
                uint32_t b1 = Vs[(kc + 4) * VST + nt * 8 + g];
                mma_tf32(of[0][nt], a[0][0], a[0][1], a[0][2], a[0][3], b0, b1);
                mma_tf32(of[1][nt], a[1][0], a[1][1], a[1][2], a[1][3], b0, b1);
            }
        }
        __syncthreads();   // protect Ks/Vs before next tile store
    }

    // epilogue
#pragma unroll
    for (int mt = 0; mt < 2; mt++) {
        float inv0 = 1.f / lrow[mt][0], inv1 = 1.f / lrow[mt][1];
        int r0 = qrow0 + mt * 16;
#pragma unroll
        for (int nt = 0; nt < 8; nt++) {
            size_t c = hoff + nt * 8 + 2 * tg;
            *(float2*)&o[(size_t)r0 * DM + c] =
                make_float2(of[mt][nt][0] * inv0, of[mt][nt][1] * inv0);
            *(float2*)&o[(size_t)(r0 + 8) * DM + c] =
                make_float2(of[mt][nt][2] * inv1, of[mt][nt][3] * inv1);
        }
    }
}

// ---------------------------------------------------------------------------
// Launch
// ---------------------------------------------------------------------------
extern "C" void kernel_launch(void* const* d_in, const int* in_sizes, int n_in,
                              void* d_out, int out_size)
{
    const float* Q  = (const float*)d_in[0];
    const float* K  = (const float*)d_in[1];
    const float* V  = (const float*)d_in[2];
    const float* Wq = (const float*)d_in[3];
    const float* Wk = (const float*)d_in[4];
    const float* Wv = (const float*)d_in[5];
    const float* Wo = (const float*)d_in[6];
    const float* bo = (const float*)d_in[7];
    float* out = (float*)d_out;

    float *gq, *gk, *gv, *ga;
    cudaGetSymbolAddress((void**)&gq, g_q);
    cudaGetSymbolAddress((void**)&gk, g_k);
    cudaGetSymbolAddress((void**)&gv, g_v);
    cudaGetSymbolAddress((void**)&ga, g_att);

    static bool attr_set = false;
    if (!attr_set) {
        cudaFuncSetAttribute(attn_mma,
                             cudaFuncAttributeMaxDynamicSharedMemorySize,
                             ATTN_SMEM);
        attr_set = true;
    }

    dim3 gproj(DM / 64, S_LEN / 128);   // (12, 32)
    gemm_mma<<<gproj, 256>>>(Q, Wq, nullptr, gq, S_LEN, DM, DM);
    gemm_mma<<<gproj, 256>>>(K, Wk, nullptr, gk, S_LEN, DM, DM);
    gemm_mma<<<gproj, 256>>>(V, Wv, nullptr, gv, S_LEN, DM, DM);

    dim3 gattn(S_LEN / 128, NH);        // (32, 12)
    attn_mma<<<gattn, 128, ATTN_SMEM>>>(gq, gk, gv, ga);

    gemm_mma<<<gproj, 256>>>(ga, Wo, bo, out, S_LEN, DM, DM);
}

// round 7
// speedup vs baseline: 1.7098x; 1.1083x over previous
#include <cuda_runtime.h>
#include <stdint.h>

#define S_LEN 4096
#define DM    768
#define NH    12
#define HD    64

// Scratch (no cudaMalloc allowed)
__device__ float g_q[S_LEN * DM];
__device__ float g_k[S_LEN * DM];
__device__ float g_v[S_LEN * DM];
__device__ float g_att[S_LEN * DM];

__device__ __forceinline__ uint32_t f2tf(float x) {
    uint32_t r;
    asm("cvt.rna.tf32.f32 %0, %1;" : "=r"(r) : "f"(x));
    return r;
}

__device__ __forceinline__ void mma_tf32(float c[4],
    uint32_t a0, uint32_t a1, uint32_t a2, uint32_t a3,
    uint32_t b0, uint32_t b1)
{
    asm volatile(
        "mma.sync.aligned.m16n8k8.row.col.f32.tf32.tf32.f32 "
        "{%0,%1,%2,%3}, {%4,%5,%6,%7}, {%8,%9}, {%0,%1,%2,%3};"
        : "+f"(c[0]), "+f"(c[1]), "+f"(c[2]), "+f"(c[3])
        : "r"(a0), "r"(a1), "r"(a2), "r"(a3), "r"(b0), "r"(b1));
}

// ---------------------------------------------------------------------------
// GEMM body: C[M,N] = A[M,K] @ B[K,N] (+bias). Block 128x64, Ktile 32,
// 128 threads = 4 warps x (32 rows x 64 cols). B-fragments amortized over
// 2 m-tiles -> 1.5 LDS/mma. Register prefetch of next tile.
// ---------------------------------------------------------------------------
#define AST 36
#define BST 72

__device__ __forceinline__ void gemm_body(
    const float* __restrict__ A, const float* __restrict__ B,
    const float* __restrict__ bias, float* __restrict__ C,
    int M, int N, int K, int bx, int by)
{
    __shared__ uint32_t As[128 * AST];
    __shared__ uint32_t Bs[32 * BST];

    const int tid  = threadIdx.x;
    const int warp = tid >> 5, lane = tid & 31;
    const int g = lane >> 2, tg = lane & 3;
    const int m0 = by * 128, n0 = bx * 64;
    const int wbase = warp * 32;

    float acc[2][8][4];
#pragma unroll
    for (int mt = 0; mt < 2; mt++)
#pragma unroll
        for (int nt = 0; nt < 8; nt++)
#pragma unroll
            for (int c = 0; c < 4; c++) acc[mt][nt][c] = 0.f;

    float4 ra[8], rb[4];
#pragma unroll
    for (int it = 0; it < 8; it++) {
        int idx = it * 128 + tid;
        int r = idx >> 3, c4 = (idx & 7) * 4;
        ra[it] = *(const float4*)&A[(size_t)(m0 + r) * K + c4];
    }
#pragma unroll
    for (int it = 0; it < 4; it++) {
        int idx = it * 128 + tid;
        int r = idx >> 4, c4 = (idx & 15) * 4;
        rb[it] = *(const float4*)&B[(size_t)r * N + n0 + c4];
    }

    for (int k0 = 0; k0 < K; k0 += 32) {
        // stage current tile
#pragma unroll
        for (int it = 0; it < 8; it++) {
            int idx = it * 128 + tid;
            int r = idx >> 3, c4 = (idx & 7) * 4;
            *(uint4*)&As[r * AST + c4] =
                make_uint4(f2tf(ra[it].x), f2tf(ra[it].y), f2tf(ra[it].z), f2tf(ra[it].w));
        }
#pragma unroll
        for (int it = 0; it < 4; it++) {
            int idx = it * 128 + tid;
            int r = idx >> 4, c4 = (idx & 15) * 4;
            *(uint4*)&Bs[r * BST + c4] =
                make_uint4(f2tf(rb[it].x), f2tf(rb[it].y), f2tf(rb[it].z), f2tf(rb[it].w));
        }
        __syncthreads();

        // prefetch next tile
        if (k0 + 32 < K) {
#pragma unroll
            for (int it = 0; it < 8; it++) {
                int idx = it * 128 + tid;
                int r = idx >> 3, c4 = (idx & 7) * 4;
                ra[it] = *(const float4*)&A[(size_t)(m0 + r) * K + k0 + 32 + c4];
            }
#pragma unroll
            for (int it = 0; it < 4; it++) {
                int idx = it * 128 + tid;
                int r = idx >> 4, c4 = (idx & 15) * 4;
                rb[it] = *(const float4*)&B[(size_t)(k0 + 32 + r) * N + n0 + c4];
            }
        }

#pragma unroll
        for (int kk = 0; kk < 4; kk++) {
            int kc = kk * 8 + tg;
            uint32_t a[2][4];
#pragma unroll
            for (int mt = 0; mt < 2; mt++) {
                int r = wbase + mt * 16 + g;
                a[mt][0] = As[r * AST + kc];
                a[mt][1] = As[(r + 8) * AST + kc];
                a[mt][2] = As[r * AST + kc + 4];
                a[mt][3] = As[(r + 8) * AST + kc + 4];
            }
#pragma unroll
            for (int nt = 0; nt < 8; nt++) {
                int c = nt * 8 + g;
                uint32_t b0 = Bs[(kk * 8 + tg) * BST + c];
                uint32_t b1 = Bs[(kk * 8 + tg + 4) * BST + c];
                mma_tf32(acc[0][nt], a[0][0], a[0][1], a[0][2], a[0][3], b0, b1);
                mma_tf32(acc[1][nt], a[1][0], a[1][1], a[1][2], a[1][3], b0, b1);
            }
        }
        __syncthreads();
    }

#pragma unroll
    for (int mt = 0; mt < 2; mt++) {
#pragma unroll
        for (int nt = 0; nt < 8; nt++) {
            int r = m0 + wbase + mt * 16 + g;
            int c = n0 + nt * 8 + 2 * tg;
            float b0 = 0.f, b1 = 0.f;
            if (bias) { b0 = bias[c]; b1 = bias[c + 1]; }
            *(float2*)&C[(size_t)r * N + c] =
                make_float2(acc[mt][nt][0] + b0, acc[mt][nt][1] + b1);
            *(float2*)&C[(size_t)(r + 8) * N + c] =
                make_float2(acc[mt][nt][2] + b0, acc[mt][nt][3] + b1);
        }
    }
}

// Fused Q/K/V projections: blockIdx.z selects (A, W, C) triple.
__global__ __launch_bounds__(128) void proj3_mma(
    const float* __restrict__ Q, const float* __restrict__ K,
    const float* __restrict__ V,
    const float* __restrict__ Wq, const float* __restrict__ Wk,
    const float* __restrict__ Wv,
    float* __restrict__ gq, float* __restrict__ gk, float* __restrict__ gv)
{
    const float* A;
    const float* B;
    float* C;
    if (blockIdx.z == 0)      { A = Q; B = Wq; C = gq; }
    else if (blockIdx.z == 1) { A = K; B = Wk; C = gk; }
    else                      { A = V; B = Wv; C = gv; }
    gemm_body(A, B, nullptr, C, S_LEN, DM, DM, blockIdx.x, blockIdx.y);
}

// Output projection with bias.
__global__ __launch_bounds__(128) void gemm_bias_mma(
    const float* __restrict__ A, const float* __restrict__ B,
    const float* __restrict__ bias, float* __restrict__ C)
{
    gemm_body(A, B, bias, C, S_LEN, DM, DM, blockIdx.x, blockIdx.y);
}

// ---------------------------------------------------------------------------
// Flash attention: byte-identical to round 6 (known good, 285us).
// ---------------------------------------------------------------------------
#define QST 68
#define KST 68
#define VST 72
#define PST 68
#define ATTN_SMEM ((128*QST + 64*KST + 64*VST + 128*PST) * 4)  // 105472 B

__global__ __launch_bounds__(128, 2) void attn_mma(
    const float* __restrict__ q, const float* __restrict__ k,
    const float* __restrict__ v, float* __restrict__ o)
{
    extern __shared__ uint32_t sm[];
    uint32_t* Qs = sm;                  // [q][d]   128 x QST
    uint32_t* Ks = Qs + 128 * QST;      // [key][d]  64 x KST
    uint32_t* Vs = Ks + 64 * KST;       // [key][dv] 64 x VST
    uint32_t* Ps = Vs + 64 * VST;       // [q][key] 128 x PST

    const int h = blockIdx.y;
    const int t = blockIdx.x;
    const int iq = (t & 1) ? (31 - (t >> 1)) : (t >> 1);  // heavy/light interleave
    const int tid = threadIdx.x, warp = tid >> 5, lane = tid & 31;
    const int g = lane >> 2, tg = lane & 3;
    const size_t hoff = (size_t)h * HD;
    const int wbase = warp * 32;
    const int qrow0 = iq * 128 + wbase + g;

    const int skey = tid >> 4;
    const int sd4  = (tid & 15) * 4;

#pragma unroll
    for (int it = 0; it < 16; it++) {
        int idx = it * 128 + tid;
        int r = idx >> 4, d4 = (idx & 15) * 4;
        float4 val = *(const float4*)&q[(size_t)(iq * 128 + r) * DM + hoff + d4];
        *(uint4*)&Qs[r * QST + d4] =
            make_uint4(f2tf(val.x), f2tf(val.y), f2tf(val.z), f2tf(val.w));
    }

    float of[2][8][4];
#pragma unroll
    for (int mt = 0; mt < 2; mt++)
#pragma unroll
        for (int nt = 0; nt < 8; nt++)
#pragma unroll
            for (int c = 0; c < 4; c++) of[mt][nt][c] = 0.f;
    float mrow[2][2], lrow[2][2];
#pragma unroll
    for (int mt = 0; mt < 2; mt++) {
        mrow[mt][0] = mrow[mt][1] = -1e30f;
        lrow[mt][0] = lrow[mt][1] = 0.f;
    }

    float4 pk[8], pv[8];
#pragma unroll
    for (int it = 0; it < 8; it++) {
        size_t gidx = hoff + (size_t)(it * 8 + skey) * DM + sd4;
        pk[it] = *(const float4*)&k[gidx];
        pv[it] = *(const float4*)&v[gidx];
    }

    __syncthreads();

    const int ktmax = 2 * iq + 1;
    for (int kt = 0; kt <= ktmax; kt++) {
#pragma unroll
        for (int it = 0; it < 8; it++) {
            int key = it * 8 + skey;
            *(uint4*)&Ks[key * KST + sd4] =
                make_uint4(f2tf(pk[it].x), f2tf(pk[it].y), f2tf(pk[it].z), f2tf(pk[it].w));
            *(uint4*)&Vs[key * VST + sd4] =
                make_uint4(f2tf(pv[it].x), f2tf(pv[it].y), f2tf(pv[it].z), f2tf(pv[it].w));
        }
        __syncthreads();

        float s[2][8][4];
#pragma unroll
        for (int mt = 0; mt < 2; mt++)
#pragma unroll
            for (int nt = 0; nt < 8; nt++)
#pragma unroll
                for (int c = 0; c < 4; c++) s[mt][nt][c] = 0.f;

#pragma unroll
        for (int ks = 0; ks < 8; ks++) {
            int kc = ks * 8 + tg;
            uint32_t a[2][4];
#pragma unroll
            for (int mt = 0; mt < 2; mt++) {
                int wr = wbase + mt * 16 + g;
                a[mt][0] = Qs[wr * QST + kc];
                a[mt][1] = Qs[(wr + 8) * QST + kc];
                a[mt][2] = Qs[wr * QST + kc + 4];
                a[mt][3] = Qs[(wr + 8) * QST + kc + 4];
            }
#pragma unroll
            for (int nt = 0; nt < 8; nt++) {
                uint32_t b0 = Ks[(nt * 8 + g) * KST + kc];
                uint32_t b1 = Ks[(nt * 8 + g) * KST + kc + 4];
                mma_tf32(s[0][nt], a[0][0], a[0][1], a[0][2], a[0][3], b0, b1);
                mma_tf32(s[1][nt], a[1][0], a[1][1], a[1][2], a[1][3], b0, b1);
            }
        }

        const bool need_mask = (kt >= 2 * iq);
#pragma unroll
        for (int mt = 0; mt < 2; mt++) {
            int r0 = qrow0 + mt * 16;
#pragma unroll
            for (int nt = 0; nt < 8; nt++) {
                s[mt][nt][0] *= 0.125f; s[mt][nt][1] *= 0.125f;
                s[mt][nt][2] *= 0.125f; s[mt][nt][3] *= 0.125f;
                if (need_mask) {
                    int col = kt * 64 + nt * 8 + 2 * tg;
                    if (col     > r0)     s[mt][nt][0] = -1e30f;
                    if (col + 1 > r0)     s[mt][nt][1] = -1e30f;
                    if (col     > r0 + 8) s[mt][nt][2] = -1e30f;
                    if (col + 1 > r0 + 8) s[mt][nt][3] = -1e30f;
                }
            }
        }

#pragma unroll
        for (int mt = 0; mt < 2; mt++) {
            float rm0 = -1e30f, rm1 = -1e30f;
#pragma unroll
            for (int nt = 0; nt < 8; nt++) {
                rm0 = fmaxf(rm0, fmaxf(s[mt][nt][0], s[mt][nt][1]));
                rm1 = fmaxf(rm1, fmaxf(s[mt][nt][2], s[mt][nt][3]));
            }
#pragma unroll
            for (int off = 1; off <= 2; off <<= 1) {
                rm0 = fmaxf(rm0, __shfl_xor_sync(0xFFFFFFFFu, rm0, off));
                rm1 = fmaxf(rm1, __shfl_xor_sync(0xFFFFFFFFu, rm1, off));
            }
            float nm0 = fmaxf(mrow[mt][0], rm0), nm1 = fmaxf(mrow[mt][1], rm1);
            float al0 = __expf(mrow[mt][0] - nm0), al1 = __expf(mrow[mt][1] - nm1);
            float sum0 = 0.f, sum1 = 0.f;
#pragma unroll
            for (int nt = 0; nt < 8; nt++) {
                s[mt][nt][0] = __expf(s[mt][nt][0] - nm0); sum0 += s[mt][nt][0];
                s[mt][nt][1] = __expf(s[mt][nt][1] - nm0); sum0 += s[mt][nt][1];
                s[mt][nt][2] = __expf(s[mt][nt][2] - nm1); sum1 += s[mt][nt][2];
                s[mt][nt][3] = __expf(s[mt][nt][3] - nm1); sum1 += s[mt][nt][3];
            }
#pragma unroll
            for (int off = 1; off <= 2; off <<= 1) {
                sum0 += __shfl_xor_sync(0xFFFFFFFFu, sum0, off);
                sum1 += __shfl_xor_sync(0xFFFFFFFFu, sum1, off);
            }
            lrow[mt][0] = lrow[mt][0] * al0 + sum0;
            lrow[mt][1] = lrow[mt][1] * al1 + sum1;
            mrow[mt][0] = nm0;  mrow[mt][1] = nm1;
#pragma unroll
            for (int nt = 0; nt < 8; nt++) {
                of[mt][nt][0] *= al0; of[mt][nt][1] *= al0;
                of[mt][nt][2] *= al1; of[mt][nt][3] *= al1;
            }
        }

#pragma unroll
        for (int mt = 0; mt < 2; mt++) {
            int wr = wbase + mt * 16 + g;
#pragma unroll
            for (int nt = 0; nt < 8; nt++) {
                int pc = nt * 8 + 2 * tg;
                *(uint2*)&Ps[wr * PST + pc] =
                    make_uint2(f2tf(s[mt][nt][0]), f2tf(s[mt][nt][1]));
                *(uint2*)&Ps[(wr + 8) * PST + pc] =
                    make_uint2(f2tf(s[mt][nt][2]), f2tf(s[mt][nt][3]));
            }
        }
        __syncwarp();

        if (kt < ktmax) {
#pragma unroll
            for (int it = 0; it < 8; it++) {
                size_t gidx = hoff + (size_t)((kt + 1) * 64 + it * 8 + skey) * DM + sd4;
                pk[it] = *(const float4*)&k[gidx];
                pv[it] = *(const float4*)&v[gidx];
            }
        }

#pragma unroll
        for (int ks = 0; ks < 8; ks++) {
            int kc = ks * 8 + tg;
            uint32_t a[2][4];
#pragma unroll
            for (int mt = 0; mt < 2; mt++) {
                int wr = wbase + mt * 16 + g;
                a[mt][0] = Ps[wr * PST + kc];
                a[mt][1] = Ps[(wr + 8) * PST + kc];
                a[mt][2] = Ps[wr * PST + kc + 4];
                a[mt][3] = Ps[(wr + 8) * PST + kc + 4];
            }
#pragma unroll
            for (int nt = 0; nt < 8; nt++) {
                uint32_t b0 = Vs[kc * VST + nt * 8 + g];
                uint32_t b1 = Vs[(kc + 4) * VST + nt * 8 + g];
                mma_tf32(of[0][nt], a[0][0], a[0][1], a[0][2], a[0][3], b0, b1);
                mma_tf32(of[1][nt], a[1][0], a[1][1], a[1][2], a[1][3], b0, b1);
            }
        }
        __syncthreads();
    }

#pragma unroll
    for (int mt = 0; mt < 2; mt++) {
        float inv0 = 1.f / lrow[mt][0], inv1 = 1.f / lrow[mt][1];
        int r0 = qrow0 + mt * 16;
#pragma unroll
        for (int nt = 0; nt < 8; nt++) {
            size_t c = hoff + nt * 8 + 2 * tg;
            *(float2*)&o[(size_t)r0 * DM + c] =
                make_float2(of[mt][nt][0] * inv0, of[mt][nt][1] * inv0);
            *(float2*)&o[(size_t)(r0 + 8) * DM + c] =
                make_float2(of[mt][nt][2] * inv1, of[mt][nt][3] * inv1);
        }
    }
}

// ---------------------------------------------------------------------------
// Launch
// ---------------------------------------------------------------------------
extern "C" void kernel_launch(void* const* d_in, const int* in_sizes, int n_in,
                              void* d_out, int out_size)
{
    const float* Q  = (const float*)d_in[0];
    const float* K  = (const float*)d_in[1];
    const float* V  = (const float*)d_in[2];
    const float* Wq = (const float*)d_in[3];
    const float* Wk = (const float*)d_in[4];
    const float* Wv = (const float*)d_in[5];
    const float* Wo = (const float*)d_in[6];
    const float* bo = (const float*)d_in[7];
    float* out = (float*)d_out;

    float *gq, *gk, *gv, *ga;
    cudaGetSymbolAddress((void**)&gq, g_q);
    cudaGetSymbolAddress((void**)&gk, g_k);
    cudaGetSymbolAddress((void**)&gv, g_v);
    cudaGetSymbolAddress((void**)&ga, g_att);

    static bool attr_set = false;
    if (!attr_set) {
        cudaFuncSetAttribute(attn_mma,
                             cudaFuncAttributeMaxDynamicSharedMemorySize,
                             ATTN_SMEM);
        attr_set = true;
    }

    dim3 gproj(DM / 64, S_LEN / 128, 3);   // (12, 32, 3) fused QKV
    proj3_mma<<<gproj, 128>>>(Q, K, V, Wq, Wk, Wv, gq, gk, gv);

    dim3 gattn(S_LEN / 128, NH);           // (32, 12)
    attn_mma<<<gattn, 128, ATTN_SMEM>>>(gq, gk, gv, ga);

    dim3 gout(DM / 64, S_LEN / 128);       // (12, 32)
    gemm_bias_mma<<<gout, 128>>>(ga, Wo, bo, out);
}